// round 2
// baseline (speedup 1.0000x reference)
#include <cuda_runtime.h>
#include <cuda_bf16.h>
#include <cstdint>
#include <math.h>

// Problem constants
#define BB 4
#define NN 4096
#define DD 4096
#define EE 64
#define TOKENS (BB*NN)   // 16384

// -------- scratch (no allocations allowed) --------
__device__ float          g_probsT[BB*EE*NN];   // [b][e][n], 4 MB
__device__ unsigned short g_rank  [BB*EE*NN];   // token indices sorted desc per (b,e), 2 MB

// -------- packed fp32x2 FMA --------
__device__ __forceinline__ void fma2(unsigned long long &acc,
                                     unsigned long long a,
                                     unsigned long long b) {
#if __CUDA_ARCH__ >= 1000
    asm("fma.rn.f32x2 %0, %1, %2, %0;" : "+l"(acc) : "l"(a), "l"(b));
#else
    float2 av = *reinterpret_cast<float2*>(&a);
    float2 bv = *reinterpret_cast<float2*>(&b);
    float2 cv = *reinterpret_cast<float2*>(&acc);
    cv.x = fmaf(av.x, bv.x, cv.x);
    cv.y = fmaf(av.y, bv.y, cv.y);
    acc = *reinterpret_cast<unsigned long long*>(&cv);
#endif
}

// ============================================================
// Kernel 1: logits GEMM (fp32) + softmax, writes probsT [b][e][n]
// Block: 64 tokens x 64 experts, 256 threads, thread = 4 tok x 4 exp.
// ============================================================
#define KC 32
#define XS_STRIDE 36   // pad: mult of 4 (float4 aligned), not mult of 32 (bank spread)

__global__ __launch_bounds__(256, 2)
void router_gemm_softmax(const float* __restrict__ x, const float* __restrict__ W) {
    __shared__ float xs[64 * XS_STRIDE];
    __shared__ float ws[64 * XS_STRIDE];
    __shared__ float ls[64 * 65];

    const int tid = threadIdx.x;
    const int tokBase = blockIdx.x * 64;          // global token
    const int b  = tokBase >> 12;                 // tokBase / NN
    const int nb = tokBase & (NN - 1);

    const int tx = tid & 15;   // expert group
    const int ty = tid >> 4;   // token group

    unsigned long long acc[4][4];
#pragma unroll
    for (int i = 0; i < 4; i++)
#pragma unroll
        for (int j = 0; j < 4; j++) acc[i][j] = 0ULL;

    for (int kc = 0; kc < DD; kc += KC) {
        __syncthreads();
        // load x tile: 64 rows x 32 cols (512 float4, 2 per thread)
#pragma unroll
        for (int r = 0; r < 2; r++) {
            int idx = tid + r * 256;
            int row = idx >> 3;
            int c4  = idx & 7;
            float4 v = *reinterpret_cast<const float4*>(
                x + (size_t)(tokBase + row) * DD + kc + c4 * 4);
            *reinterpret_cast<float4*>(&xs[row * XS_STRIDE + c4 * 4]) = v;
        }
        // load W tile
#pragma unroll
        for (int r = 0; r < 2; r++) {
            int idx = tid + r * 256;
            int row = idx >> 3;
            int c4  = idx & 7;
            float4 v = *reinterpret_cast<const float4*>(
                W + (size_t)row * DD + kc + c4 * 4);
            *reinterpret_cast<float4*>(&ws[row * XS_STRIDE + c4 * 4]) = v;
        }
        __syncthreads();

#pragma unroll
        for (int kk = 0; kk < KC; kk += 4) {
            ulonglong2 xv[4], wv[4];
#pragma unroll
            for (int i = 0; i < 4; i++)
                xv[i] = *reinterpret_cast<const ulonglong2*>(
                    &xs[(ty * 4 + i) * XS_STRIDE + kk]);
#pragma unroll
            for (int j = 0; j < 4; j++)
                wv[j] = *reinterpret_cast<const ulonglong2*>(
                    &ws[(tx * 4 + j) * XS_STRIDE + kk]);
#pragma unroll
            for (int i = 0; i < 4; i++)
#pragma unroll
                for (int j = 0; j < 4; j++) {
                    fma2(acc[i][j], xv[i].x, wv[j].x);
                    fma2(acc[i][j], xv[i].y, wv[j].y);
                }
        }
    }

    // reduce even/odd halves, stage logits to smem
#pragma unroll
    for (int i = 0; i < 4; i++)
#pragma unroll
        for (int j = 0; j < 4; j++) {
            unsigned long long a = acc[i][j];
            float lo = __uint_as_float((unsigned)(a & 0xFFFFFFFFULL));
            float hi = __uint_as_float((unsigned)(a >> 32));
            ls[(ty * 4 + i) * 65 + (tx * 4 + j)] = lo + hi;
        }
    __syncthreads();

    // softmax per token (threads 0..63), then coalesced transposed store
    if (tid < 64) {
        const int t = tid;
        float m = -INFINITY;
#pragma unroll
        for (int e = 0; e < EE; e++) m = fmaxf(m, ls[t * 65 + e]);
        float s = 0.f;
#pragma unroll
        for (int e = 0; e < EE; e++) {
            float v = expf(ls[t * 65 + e] - m);
            ls[t * 65 + e] = v;
            s += v;
        }
        float inv = 1.0f / s;
#pragma unroll
        for (int e = 0; e < EE; e++) {
            g_probsT[((size_t)(b * EE + e) << 12) + nb + t] = ls[t * 65 + e] * inv;
        }
    }
}

// ============================================================
// Kernel 2: per-(b,e) descending bitonic sort of probs row,
// tie-break lower token index first (matches lax.top_k).
// ============================================================
#define SORT_T 512

__global__ __launch_bounds__(SORT_T)
void expert_sort() {
    __shared__ unsigned long long keys[NN];
    const int tid = threadIdx.x;
    const int row = blockIdx.x;     // b*EE + e
    const size_t base = (size_t)row << 12;

    for (int i = tid; i < NN; i += SORT_T) {
        unsigned bits = __float_as_uint(g_probsT[base + i]);  // probs >= 0 -> bit order == value order
        keys[i] = ((unsigned long long)bits << 32) | (unsigned)(NN - 1 - i);
    }
    __syncthreads();

    for (int k = 2; k <= NN; k <<= 1) {
        for (int j = k >> 1; j > 0; j >>= 1) {
            for (int m = tid; m < NN; m += SORT_T) {
                int ixj = m ^ j;
                if (ixj > m) {
                    unsigned long long a = keys[m], c = keys[ixj];
                    bool up = ((m & k) == 0);       // "up" segment -> descending
                    if (up ? (a < c) : (a > c)) { keys[m] = c; keys[ixj] = a; }
                }
            }
            __syncthreads();
        }
    }

    for (int i = tid; i < NN; i += SORT_T)
        g_rank[base + i] = (unsigned short)(NN - 1 - (unsigned)(keys[i] & 0xFFFu));
}

// ============================================================
// Kernel 3: sequential expert-preferred assignment, 1 block per batch.
// out layout: [0, B*N) = M (float), [B*N, 2*B*N) = M_probs.
// ============================================================
__global__ __launch_bounds__(256)
void assign_tokens(const float* __restrict__ c, float* __restrict__ out) {
    __shared__ unsigned mask[NN / 32];
    __shared__ int s_warpsum[8];
    __shared__ int s_picked;

    const int tid = threadIdx.x;
    const int b = blockIdx.x;
    const int lane = tid & 31, wid = tid >> 5;

    for (int i = tid; i < NN / 32; i += 256) mask[i] = 0u;
    // defaults: M = 0, M_probs = probs[b, n, 0]
    for (int n = tid; n < NN; n += 256) {
        out[b * NN + n] = 0.0f;
        out[TOKENS + b * NN + n] = g_probsT[((size_t)(b * EE) << 12) + n];
    }
    __syncthreads();

    for (int j = EE - 1; j >= 0; --j) {
        int kj = (int)floorf(c[j] * (float)NN);
        if (kj <= 0) continue;
        if (kj > NN) kj = NN;
        if (tid == 0) s_picked = 0;
        __syncthreads();

        const size_t rbase = (size_t)(b * EE + j) << 12;
        for (int pos = 0; pos < NN && s_picked < kj; pos += 256) {
            int tok = -1;
            bool avail = false;
            int ti = pos + tid;
            if (ti < NN) {
                tok = g_rank[rbase + ti];
                avail = !((mask[tok >> 5] >> (tok & 31)) & 1u);
            }
            unsigned ball = __ballot_sync(0xFFFFFFFFu, avail);
            if (lane == 0) s_warpsum[wid] = __popc(ball);
            __syncthreads();
            int off = 0, total = 0;
#pragma unroll
            for (int w = 0; w < 8; w++) {
                int v = s_warpsum[w];
                if (w < wid) off += v;
                total += v;
            }
            int myrank = off + __popc(ball & ((1u << lane) - 1));
            int base = s_picked;
            if (avail && base + myrank < kj) {
                out[b * NN + tok] = (float)j;
                out[TOKENS + b * NN + tok] = g_probsT[rbase + tok];
                atomicOr(&mask[tok >> 5], 1u << (tok & 31));
            }
            __syncthreads();
            if (tid == 0) s_picked = min(base + total, kj);
            __syncthreads();
        }
        __syncthreads();
    }
}

// ============================================================
extern "C" void kernel_launch(void* const* d_in, const int* in_sizes, int n_in,
                              void* d_out, int out_size) {
    const float* x = (const float*)d_in[0];
    const float* W = (const float*)d_in[1];
    const float* c = (const float*)d_in[2];
    float* out = (float*)d_out;

    router_gemm_softmax<<<TOKENS / 64, 256>>>(x, W);
    expert_sort<<<BB * EE, SORT_T>>>();
    assign_tokens<<<BB, 256>>>(c, out);
}

// round 5
// speedup vs baseline: 2.1831x; 2.1831x over previous
#include <cuda_runtime.h>
#include <cuda_bf16.h>
#include <cstdint>
#include <math.h>

// ---------------- problem constants ----------------
#define BB 4
#define NN 4096
#define DD 4096
#define EE 64
#define TOKENS (BB*NN)     // 16384

#define KC 64              // K per chunk
#define NCHUNK (DD/KC)     // 64
#define TILE_M 128         // tokens per CTA

// per stage: A planes 3*16KB (128x64 bf16 h/m/l) + B planes 3*8KB (64x64 bf16)
#define A_PLANE 16384
#define B_PLANE 8192
#define B_BASE  (3*A_PLANE)          // 49152
#define STG_BYTES (3*A_PLANE + 3*B_PLANE)   // 73728
#define SMEM_DYN (2*STG_BYTES + 1024)

// ---------------- scratch ----------------
__device__ float          g_probsT[BB*EE*NN];     // [b][e][n]  4MB
__device__ unsigned short g_rank  [BB*EE*NN];     // sorted token ids per (b,e)  2MB
__device__ __nv_bfloat16  g_Wh[EE*DD];
__device__ __nv_bfloat16  g_Wm[EE*DD];
__device__ __nv_bfloat16  g_Wl[EE*DD];

// ---------------- helpers ----------------
__device__ __forceinline__ uint32_t smem_u32(const void* p) {
    uint32_t a;
    asm("{ .reg .u64 t; cvta.to.shared.u64 t, %1; cvt.u32.u64 %0, t; }" : "=r"(a) : "l"(p));
    return a;
}
#define SWZ(off) ((off) ^ (((off) >> 3) & 0x70))

__device__ __forceinline__ void sts64(uint32_t addr, uint32_t a, uint32_t b) {
    asm volatile("st.shared.v2.b32 [%0], {%1,%2};" :: "r"(addr), "r"(a), "r"(b));
}
__device__ __forceinline__ uint32_t pk2(float a, float b) {
    __nv_bfloat162 t = __floats2bfloat162_rn(a, b);   // low = a, high = b
    return *reinterpret_cast<uint32_t*>(&t);
}
__device__ __forceinline__ void ldsm4(uint32_t addr, uint32_t* r) {
    asm volatile("ldmatrix.sync.aligned.m8n8.x4.shared.b16 {%0,%1,%2,%3}, [%4];"
        : "=r"(r[0]), "=r"(r[1]), "=r"(r[2]), "=r"(r[3]) : "r"(addr));
}
__device__ __forceinline__ void mma16816(float* c, const uint32_t* a, const uint32_t* b) {
    asm volatile(
        "mma.sync.aligned.m16n8k16.row.col.f32.bf16.bf16.f32 "
        "{%0,%1,%2,%3},{%4,%5,%6,%7},{%8,%9},{%0,%1,%2,%3};"
        : "+f"(c[0]), "+f"(c[1]), "+f"(c[2]), "+f"(c[3])
        : "r"(a[0]), "r"(a[1]), "r"(a[2]), "r"(a[3]), "r"(b[0]), "r"(b[1]));
}

// ============================================================
// Kernel 0: split W (fp32) into 3 bf16 residual terms.
// ============================================================
__global__ __launch_bounds__(256)
void split_w(const float* __restrict__ W) {
    int i = blockIdx.x * 256 + threadIdx.x;
    if (i >= EE * DD) return;
    float w = W[i];
    __nv_bfloat16 h = __float2bfloat16(w);
    float r = w - __bfloat162float(h);
    __nv_bfloat16 m = __float2bfloat16(r);
    float r2 = r - __bfloat162float(m);
    g_Wh[i] = h;
    g_Wm[i] = m;
    g_Wl[i] = __float2bfloat16(r2);
}

// ============================================================
// Kernel 1: mma.sync bf16x3 router GEMM + fused softmax.
// CTA: 128 tokens x 64 experts, 256 threads (8 warps).
// Warp w: token rows [16w, 16w+16), all 64 expert cols.
// ============================================================
__global__ __launch_bounds__(256, 1)
void router_gemm_mma(const float* __restrict__ x) {
    extern __shared__ char dsm[];
    const int tid  = threadIdx.x;
    const int wid  = tid >> 5;
    const int lane = tid & 31;
    const int tok0 = blockIdx.x * TILE_M;

    uint32_t sbase = smem_u32(dsm);
    sbase = (sbase + 1023) & ~1023u;

    float acc[8][4];
#pragma unroll
    for (int t = 0; t < 8; t++)
#pragma unroll
        for (int i = 0; i < 4; i++) acc[t][i] = 0.f;

    // ldmatrix per-lane address components
    const int ra    = wid * 16 + (lane & 15);          // A row
    const int ahalf = (lane >> 4) * 16;                // A k-half bytes
    const int rb    = (lane & 7) + ((lane >> 4) & 1) * 8;  // B row within 16
    const int bhalf = ((lane >> 3) & 1) * 16;          // B k-half bytes

    // prefetch registers
    float4 xa[8];
    uint2 wbh[4], wbm[4], wbl[4];

    // ---- prologue: load chunk 0 ----
#pragma unroll
    for (int it = 0; it < 8; ++it) {
        int lin = tid + it * 256, row = lin >> 4, c4 = lin & 15;
        xa[it] = *reinterpret_cast<const float4*>(
            x + (size_t)(tok0 + row) * DD + c4 * 4);
    }
#pragma unroll
    for (int it = 0; it < 4; ++it) {
        int lin = tid + it * 256, row = lin >> 4, cc = lin & 15;
        size_t off = (size_t)row * DD + cc * 4;
        wbh[it] = *reinterpret_cast<const uint2*>(g_Wh + off);
        wbm[it] = *reinterpret_cast<const uint2*>(g_Wm + off);
        wbl[it] = *reinterpret_cast<const uint2*>(g_Wl + off);
    }

#pragma unroll 1
    for (int c = 0; c < NCHUNK; ++c) {
        const uint32_t st = sbase + (c & 1) * STG_BYTES;

        // ---- split + STS chunk c from registers ----
#pragma unroll
        for (int it = 0; it < 8; ++it) {
            int lin = tid + it * 256, row = lin >> 4, c4 = lin & 15;
            uint32_t boff = SWZ(row * 128 + c4 * 8);
            float v0 = xa[it].x, v1 = xa[it].y, v2 = xa[it].z, v3 = xa[it].w;
            float h0 = __bfloat162float(__float2bfloat16(v0));
            float h1 = __bfloat162float(__float2bfloat16(v1));
            float h2 = __bfloat162float(__float2bfloat16(v2));
            float h3 = __bfloat162float(__float2bfloat16(v3));
            float r0 = v0 - h0, r1 = v1 - h1, r2 = v2 - h2, r3 = v3 - h3;
            float m0 = __bfloat162float(__float2bfloat16(r0));
            float m1 = __bfloat162float(__float2bfloat16(r1));
            float m2 = __bfloat162float(__float2bfloat16(r2));
            float m3 = __bfloat162float(__float2bfloat16(r3));
            sts64(st +            boff, pk2(h0, h1), pk2(h2, h3));
            sts64(st + A_PLANE  + boff, pk2(m0, m1), pk2(m2, m3));
            sts64(st + 2*A_PLANE+ boff, pk2(r0 - m0, r1 - m1), pk2(r2 - m2, r3 - m3));
        }
#pragma unroll
        for (int it = 0; it < 4; ++it) {
            int lin = tid + it * 256, row = lin >> 4, cc = lin & 15;
            uint32_t boff = SWZ(row * 128 + cc * 8);
            sts64(st + B_BASE            + boff, wbh[it].x, wbh[it].y);
            sts64(st + B_BASE + B_PLANE  + boff, wbm[it].x, wbm[it].y);
            sts64(st + B_BASE + 2*B_PLANE+ boff, wbl[it].x, wbl[it].y);
        }
        __syncthreads();

        // ---- prefetch chunk c+1 (hidden under MMA below) ----
        if (c + 1 < NCHUNK) {
            const int kc = (c + 1) * KC;
#pragma unroll
            for (int it = 0; it < 8; ++it) {
                int lin = tid + it * 256, row = lin >> 4, c4 = lin & 15;
                xa[it] = *reinterpret_cast<const float4*>(
                    x + (size_t)(tok0 + row) * DD + kc + c4 * 4);
            }
#pragma unroll
            for (int it = 0; it < 4; ++it) {
                int lin = tid + it * 256, row = lin >> 4, cc = lin & 15;
                size_t off = (size_t)row * DD + kc + cc * 4;
                wbh[it] = *reinterpret_cast<const uint2*>(g_Wh + off);
                wbm[it] = *reinterpret_cast<const uint2*>(g_Wm + off);
                wbl[it] = *reinterpret_cast<const uint2*>(g_Wl + off);
            }
        }

        // ---- MMA on chunk c ----
#pragma unroll
        for (int k = 0; k < 4; ++k) {
            uint32_t Ah[4], Am[4], Al[4];
            uint32_t aoff = SWZ(ra * 128 + k * 32 + ahalf);
            ldsm4(st +             aoff, Ah);
            ldsm4(st + A_PLANE   + aoff, Am);
            ldsm4(st + 2*A_PLANE + aoff, Al);

            uint32_t Bf[16];
            // Bh: pairs with Ah, Am, Al
#pragma unroll
            for (int t2 = 0; t2 < 4; ++t2)
                ldsm4(st + B_BASE + SWZ((t2 * 16 + rb) * 128 + k * 32 + bhalf), Bf + 4 * t2);
#pragma unroll
            for (int nt = 0; nt < 8; ++nt) mma16816(acc[nt], Ah, Bf + 2 * nt);
#pragma unroll
            for (int nt = 0; nt < 8; ++nt) mma16816(acc[nt], Am, Bf + 2 * nt);
#pragma unroll
            for (int nt = 0; nt < 8; ++nt) mma16816(acc[nt], Al, Bf + 2 * nt);
            // Bm: pairs with Ah, Am
#pragma unroll
            for (int t2 = 0; t2 < 4; ++t2)
                ldsm4(st + B_BASE + B_PLANE + SWZ((t2 * 16 + rb) * 128 + k * 32 + bhalf), Bf + 4 * t2);
#pragma unroll
            for (int nt = 0; nt < 8; ++nt) mma16816(acc[nt], Ah, Bf + 2 * nt);
#pragma unroll
            for (int nt = 0; nt < 8; ++nt) mma16816(acc[nt], Am, Bf + 2 * nt);
            // Bl: pairs with Ah
#pragma unroll
            for (int t2 = 0; t2 < 4; ++t2)
                ldsm4(st + B_BASE + 2*B_PLANE + SWZ((t2 * 16 + rb) * 128 + k * 32 + bhalf), Bf + 4 * t2);
#pragma unroll
            for (int nt = 0; nt < 8; ++nt) mma16816(acc[nt], Ah, Bf + 2 * nt);
        }
        // no sync needed: next STS targets the other buffer
    }
    __syncthreads();

    // ---- epilogue: stage logits to smem (pad 65), softmax, transposed store ----
    float* ls = reinterpret_cast<float*>(dsm);   // 128*65*4 = 33.3KB
    {
        int r0 = wid * 16 + (lane >> 2);
        int cb = 2 * (lane & 3);
#pragma unroll
        for (int nt = 0; nt < 8; ++nt) {
            ls[r0 * 65 + 8 * nt + cb]           = acc[nt][0];
            ls[r0 * 65 + 8 * nt + cb + 1]       = acc[nt][1];
            ls[(r0 + 8) * 65 + 8 * nt + cb]     = acc[nt][2];
            ls[(r0 + 8) * 65 + 8 * nt + cb + 1] = acc[nt][3];
        }
    }
    __syncthreads();

    if (tid < TILE_M) {
        const int t = tid;
        float mx = -INFINITY;
#pragma unroll
        for (int e = 0; e < EE; e++) mx = fmaxf(mx, ls[t * 65 + e]);
        float sum = 0.f;
#pragma unroll
        for (int e = 0; e < EE; e++) {
            float v = expf(ls[t * 65 + e] - mx);
            ls[t * 65 + e] = v;
            sum += v;
        }
        float inv = 1.0f / sum;
        int token = tok0 + t;
        int b = token >> 12, n = token & (NN - 1);
#pragma unroll
        for (int e = 0; e < EE; e++)
            g_probsT[((size_t)(b * EE + e) << 12) + n] = ls[t * 65 + e] * inv;
    }
}

// ============================================================
// Kernel 2: per-(b,e) descending bitonic sort (tie: lower token first)
// ============================================================
#define SORT_T 512
__global__ __launch_bounds__(SORT_T)
void expert_sort() {
    __shared__ unsigned long long keys[NN];
    const int tid = threadIdx.x;
    const size_t base = (size_t)blockIdx.x << 12;

    for (int i = tid; i < NN; i += SORT_T) {
        unsigned bits = __float_as_uint(g_probsT[base + i]);  // probs > 0: bit order == value order
        keys[i] = ((unsigned long long)bits << 32) | (unsigned)(NN - 1 - i);
    }
    __syncthreads();

    for (int k = 2; k <= NN; k <<= 1) {
        for (int j = k >> 1; j > 0; j >>= 1) {
            for (int m = tid; m < NN; m += SORT_T) {
                int ixj = m ^ j;
                if (ixj > m) {
                    unsigned long long a = keys[m], c = keys[ixj];
                    bool up = ((m & k) == 0);
                    if (up ? (a < c) : (a > c)) { keys[m] = c; keys[ixj] = a; }
                }
            }
            __syncthreads();
        }
    }

    for (int i = tid; i < NN; i += SORT_T)
        g_rank[base + i] = (unsigned short)(NN - 1 - (unsigned)(keys[i] & 0xFFFu));
}

// ============================================================
// Kernel 3: sequential expert-preferred assignment (1 block / batch)
// out: [0, B*N) = M (float), [B*N, 2*B*N) = M_probs.
// ============================================================
__global__ __launch_bounds__(256)
void assign_tokens(const float* __restrict__ c, float* __restrict__ out) {
    __shared__ unsigned mask[NN / 32];
    __shared__ __align__(16) unsigned short srank[NN];
    __shared__ int s_warpsum[8];
    __shared__ int s_picked;

    const int tid = threadIdx.x;
    const int b = blockIdx.x;
    const int lane = tid & 31, wid = tid >> 5;

    for (int i = tid; i < NN / 32; i += 256) mask[i] = 0u;
    for (int n = tid; n < NN; n += 256) {
        out[b * NN + n] = 0.0f;
        out[TOKENS + b * NN + n] = g_probsT[((size_t)(b * EE) << 12) + n];
    }
    __syncthreads();

    for (int j = EE - 1; j >= 0; --j) {
        int kj = (int)floorf(c[j] * (float)NN);
        if (kj <= 0) continue;
        if (kj > NN) kj = NN;
        const size_t rbase = (size_t)(b * EE + j) << 12;

        {
            const uint2* src = reinterpret_cast<const uint2*>(g_rank + rbase);
            uint2* dst = reinterpret_cast<uint2*>(srank);
            for (int i = tid; i < NN / 4; i += 256) dst[i] = src[i];
        }
        if (tid == 0) s_picked = 0;
        __syncthreads();

        for (int pos = 0; pos < NN && s_picked < kj; pos += 256) {
            int tok = -1;
            bool avail = false;
            int ti = pos + tid;
            if (ti < NN) {
                tok = srank[ti];
                avail = !((mask[tok >> 5] >> (tok & 31)) & 1u);
            }
            unsigned ball = __ballot_sync(0xFFFFFFFFu, avail);
            if (lane == 0) s_warpsum[wid] = __popc(ball);
            __syncthreads();
            int off = 0, total = 0;
#pragma unroll
            for (int w = 0; w < 8; w++) {
                int v = s_warpsum[w];
                if (w < wid) off += v;
                total += v;
            }
            int myrank = off + __popc(ball & ((1u << lane) - 1));
            int base = s_picked;
            if (avail && base + myrank < kj) {
                out[b * NN + tok] = (float)j;
                out[TOKENS + b * NN + tok] = g_probsT[rbase + tok];
                atomicOr(&mask[tok >> 5], 1u << (tok & 31));
            }
            __syncthreads();
            if (tid == 0) s_picked = min(base + total, kj);
            __syncthreads();
        }
        __syncthreads();
    }
}

// ============================================================
extern "C" void kernel_launch(void* const* d_in, const int* in_sizes, int n_in,
                              void* d_out, int out_size) {
    const float* x = (const float*)d_in[0];
    const float* W = (const float*)d_in[1];
    const float* c = (const float*)d_in[2];
    float* out = (float*)d_out;

    cudaFuncSetAttribute(router_gemm_mma,
                         cudaFuncAttributeMaxDynamicSharedMemorySize, SMEM_DYN);

    split_w<<<(EE * DD + 255) / 256, 256>>>(W);
    router_gemm_mma<<<TOKENS / TILE_M, 256, SMEM_DYN>>>(x);
    expert_sort<<<BB * EE, SORT_T>>>();
    assign_tokens<<<BB, 256>>>(c, out);
}

// round 7
// speedup vs baseline: 2.7219x; 1.2468x over previous
#include <cuda_runtime.h>
#include <cuda_bf16.h>
#include <cstdint>
#include <math.h>

// ---------------- problem constants ----------------
#define BB 4
#define NN 4096
#define DD 4096
#define EE 64
#define TOKENS (BB*NN)     // 16384

#define KC 64              // K per chunk
#define NCHUNK (DD/KC)     // 64
#define TILE_M 128         // tokens per CTA

// per stage: A planes 3*16KB (128x64 bf16 h/m/l) + B planes 3*8KB (64x64 bf16)
#define A_PLANE 16384
#define B_PLANE 8192
#define B_BASE  (3*A_PLANE)          // 49152
#define STG_BYTES (3*A_PLANE + 3*B_PLANE)   // 73728
#define SMEM_DYN (2*STG_BYTES + 1024)

// ---------------- scratch ----------------
__device__ float          g_probsT[BB*EE*NN];     // [b][e][n]  4MB
__device__ unsigned short g_rank  [BB*EE*NN];     // sorted token ids per (b,e)  2MB
__device__ __nv_bfloat16  g_Wh[EE*DD];
__device__ __nv_bfloat16  g_Wm[EE*DD];
__device__ __nv_bfloat16  g_Wl[EE*DD];

// ---------------- helpers ----------------
__device__ __forceinline__ uint32_t smem_u32(const void* p) {
    uint32_t a;
    asm("{ .reg .u64 t; cvta.to.shared.u64 t, %1; cvt.u32.u64 %0, t; }" : "=r"(a) : "l"(p));
    return a;
}
#define SWZ(off) ((off) ^ (((off) >> 3) & 0x70))

__device__ __forceinline__ void sts64(uint32_t addr, uint32_t a, uint32_t b) {
    asm volatile("st.shared.v2.b32 [%0], {%1,%2};" :: "r"(addr), "r"(a), "r"(b));
}
__device__ __forceinline__ uint32_t pk2(float a, float b) {
    __nv_bfloat162 t = __floats2bfloat162_rn(a, b);   // low = a, high = b
    return *reinterpret_cast<uint32_t*>(&t);
}
__device__ __forceinline__ void ldsm4(uint32_t addr, uint32_t* r) {
    asm volatile("ldmatrix.sync.aligned.m8n8.x4.shared.b16 {%0,%1,%2,%3}, [%4];"
        : "=r"(r[0]), "=r"(r[1]), "=r"(r[2]), "=r"(r[3]) : "r"(addr));
}
__device__ __forceinline__ void mma16816(float* c, const uint32_t* a, const uint32_t* b) {
    asm volatile(
        "mma.sync.aligned.m16n8k16.row.col.f32.bf16.bf16.f32 "
        "{%0,%1,%2,%3},{%4,%5,%6,%7},{%8,%9},{%0,%1,%2,%3};"
        : "+f"(c[0]), "+f"(c[1]), "+f"(c[2]), "+f"(c[3])
        : "r"(a[0]), "r"(a[1]), "r"(a[2]), "r"(a[3]), "r"(b[0]), "r"(b[1]));
}

// ============================================================
// Kernel 0: split W (fp32) into 3 bf16 residual terms.
// ============================================================
__global__ __launch_bounds__(256)
void split_w(const float* __restrict__ W) {
    int i = blockIdx.x * 256 + threadIdx.x;
    if (i >= EE * DD) return;
    float w = W[i];
    __nv_bfloat16 h = __float2bfloat16(w);
    float r = w - __bfloat162float(h);
    __nv_bfloat16 m = __float2bfloat16(r);
    float r2 = r - __bfloat162float(m);
    g_Wh[i] = h;
    g_Wm[i] = m;
    g_Wl[i] = __float2bfloat16(r2);
}

// ============================================================
// Kernel 1: mma.sync bf16x3 router GEMM + fused softmax.
// CTA: 128 tokens x 64 experts, 256 threads (8 warps).
// ============================================================
__global__ __launch_bounds__(256, 1)
void router_gemm_mma(const float* __restrict__ x) {
    extern __shared__ char dsm[];
    const int tid  = threadIdx.x;
    const int wid  = tid >> 5;
    const int lane = tid & 31;
    const int tok0 = blockIdx.x * TILE_M;

    uint32_t sbase = smem_u32(dsm);
    sbase = (sbase + 1023) & ~1023u;

    float acc[8][4];
#pragma unroll
    for (int t = 0; t < 8; t++)
#pragma unroll
        for (int i = 0; i < 4; i++) acc[t][i] = 0.f;

    const int ra    = wid * 16 + (lane & 15);
    const int ahalf = (lane >> 4) * 16;
    const int rb    = (lane & 7) + ((lane >> 4) & 1) * 8;
    const int bhalf = ((lane >> 3) & 1) * 16;

    float4 xa[8];
    uint2 wbh[4], wbm[4], wbl[4];

#pragma unroll
    for (int it = 0; it < 8; ++it) {
        int lin = tid + it * 256, row = lin >> 4, c4 = lin & 15;
        xa[it] = *reinterpret_cast<const float4*>(
            x + (size_t)(tok0 + row) * DD + c4 * 4);
    }
#pragma unroll
    for (int it = 0; it < 4; ++it) {
        int lin = tid + it * 256, row = lin >> 4, cc = lin & 15;
        size_t off = (size_t)row * DD + cc * 4;
        wbh[it] = *reinterpret_cast<const uint2*>(g_Wh + off);
        wbm[it] = *reinterpret_cast<const uint2*>(g_Wm + off);
        wbl[it] = *reinterpret_cast<const uint2*>(g_Wl + off);
    }

#pragma unroll 1
    for (int c = 0; c < NCHUNK; ++c) {
        const uint32_t st = sbase + (c & 1) * STG_BYTES;

#pragma unroll
        for (int it = 0; it < 8; ++it) {
            int lin = tid + it * 256, row = lin >> 4, c4 = lin & 15;
            uint32_t boff = SWZ(row * 128 + c4 * 8);
            float v0 = xa[it].x, v1 = xa[it].y, v2 = xa[it].z, v3 = xa[it].w;
            float h0 = __bfloat162float(__float2bfloat16(v0));
            float h1 = __bfloat162float(__float2bfloat16(v1));
            float h2 = __bfloat162float(__float2bfloat16(v2));
            float h3 = __bfloat162float(__float2bfloat16(v3));
            float r0 = v0 - h0, r1 = v1 - h1, r2 = v2 - h2, r3 = v3 - h3;
            float m0 = __bfloat162float(__float2bfloat16(r0));
            float m1 = __bfloat162float(__float2bfloat16(r1));
            float m2 = __bfloat162float(__float2bfloat16(r2));
            float m3 = __bfloat162float(__float2bfloat16(r3));
            sts64(st +            boff, pk2(h0, h1), pk2(h2, h3));
            sts64(st + A_PLANE  + boff, pk2(m0, m1), pk2(m2, m3));
            sts64(st + 2*A_PLANE+ boff, pk2(r0 - m0, r1 - m1), pk2(r2 - m2, r3 - m3));
        }
#pragma unroll
        for (int it = 0; it < 4; ++it) {
            int lin = tid + it * 256, row = lin >> 4, cc = lin & 15;
            uint32_t boff = SWZ(row * 128 + cc * 8);
            sts64(st + B_BASE            + boff, wbh[it].x, wbh[it].y);
            sts64(st + B_BASE + B_PLANE  + boff, wbm[it].x, wbm[it].y);
            sts64(st + B_BASE + 2*B_PLANE+ boff, wbl[it].x, wbl[it].y);
        }
        __syncthreads();

        if (c + 1 < NCHUNK) {
            const int kc = (c + 1) * KC;
#pragma unroll
            for (int it = 0; it < 8; ++it) {
                int lin = tid + it * 256, row = lin >> 4, c4 = lin & 15;
                xa[it] = *reinterpret_cast<const float4*>(
                    x + (size_t)(tok0 + row) * DD + kc + c4 * 4);
            }
#pragma unroll
            for (int it = 0; it < 4; ++it) {
                int lin = tid + it * 256, row = lin >> 4, cc = lin & 15;
                size_t off = (size_t)row * DD + kc + cc * 4;
                wbh[it] = *reinterpret_cast<const uint2*>(g_Wh + off);
                wbm[it] = *reinterpret_cast<const uint2*>(g_Wm + off);
                wbl[it] = *reinterpret_cast<const uint2*>(g_Wl + off);
            }
        }

#pragma unroll
        for (int k = 0; k < 4; ++k) {
            uint32_t Ah[4], Am[4], Al[4];
            uint32_t aoff = SWZ(ra * 128 + k * 32 + ahalf);
            ldsm4(st +             aoff, Ah);
            ldsm4(st + A_PLANE   + aoff, Am);
            ldsm4(st + 2*A_PLANE + aoff, Al);

            uint32_t Bf[16];
#pragma unroll
            for (int t2 = 0; t2 < 4; ++t2)
                ldsm4(st + B_BASE + SWZ((t2 * 16 + rb) * 128 + k * 32 + bhalf), Bf + 4 * t2);
#pragma unroll
            for (int nt = 0; nt < 8; ++nt) mma16816(acc[nt], Ah, Bf + 2 * nt);
#pragma unroll
            for (int nt = 0; nt < 8; ++nt) mma16816(acc[nt], Am, Bf + 2 * nt);
#pragma unroll
            for (int nt = 0; nt < 8; ++nt) mma16816(acc[nt], Al, Bf + 2 * nt);
#pragma unroll
            for (int t2 = 0; t2 < 4; ++t2)
                ldsm4(st + B_BASE + B_PLANE + SWZ((t2 * 16 + rb) * 128 + k * 32 + bhalf), Bf + 4 * t2);
#pragma unroll
            for (int nt = 0; nt < 8; ++nt) mma16816(acc[nt], Ah, Bf + 2 * nt);
#pragma unroll
            for (int nt = 0; nt < 8; ++nt) mma16816(acc[nt], Am, Bf + 2 * nt);
#pragma unroll
            for (int t2 = 0; t2 < 4; ++t2)
                ldsm4(st + B_BASE + 2*B_PLANE + SWZ((t2 * 16 + rb) * 128 + k * 32 + bhalf), Bf + 4 * t2);
#pragma unroll
            for (int nt = 0; nt < 8; ++nt) mma16816(acc[nt], Ah, Bf + 2 * nt);
        }
    }
    __syncthreads();

    float* ls = reinterpret_cast<float*>(dsm);
    {
        int r0 = wid * 16 + (lane >> 2);
        int cb = 2 * (lane & 3);
#pragma unroll
        for (int nt = 0; nt < 8; ++nt) {
            ls[r0 * 65 + 8 * nt + cb]           = acc[nt][0];
            ls[r0 * 65 + 8 * nt + cb + 1]       = acc[nt][1];
            ls[(r0 + 8) * 65 + 8 * nt + cb]     = acc[nt][2];
            ls[(r0 + 8) * 65 + 8 * nt + cb + 1] = acc[nt][3];
        }
    }
    __syncthreads();

    if (tid < TILE_M) {
        const int t = tid;
        float mx = -INFINITY;
#pragma unroll
        for (int e = 0; e < EE; e++) mx = fmaxf(mx, ls[t * 65 + e]);
        float sum = 0.f;
#pragma unroll
        for (int e = 0; e < EE; e++) {
            float v = expf(ls[t * 65 + e] - mx);
            ls[t * 65 + e] = v;
            sum += v;
        }
        float inv = 1.0f / sum;
        int token = tok0 + t;
        int b = token >> 12, n = token & (NN - 1);
#pragma unroll
        for (int e = 0; e < EE; e++)
            g_probsT[((size_t)(b * EE + e) << 12) + n] = ls[t * 65 + e] * inv;
    }
}

// ============================================================
// Kernel 2: per-(b,e) descending bitonic sort (tie: lower token first)
// ============================================================
#define SORT_T 512
__global__ __launch_bounds__(SORT_T)
void expert_sort() {
    __shared__ unsigned long long keys[NN];
    const int tid = threadIdx.x;
    const size_t base = (size_t)blockIdx.x << 12;

    for (int i = tid; i < NN; i += SORT_T) {
        unsigned bits = __float_as_uint(g_probsT[base + i]);
        keys[i] = ((unsigned long long)bits << 32) | (unsigned)(NN - 1 - i);
    }
    __syncthreads();

    for (int k = 2; k <= NN; k <<= 1) {
        for (int j = k >> 1; j > 0; j >>= 1) {
            for (int m = tid; m < NN; m += SORT_T) {
                int ixj = m ^ j;
                if (ixj > m) {
                    unsigned long long a = keys[m], c = keys[ixj];
                    bool up = ((m & k) == 0);
                    if (up ? (a < c) : (a > c)) { keys[m] = c; keys[ixj] = a; }
                }
            }
            __syncthreads();
        }
    }

    for (int i = tid; i < NN; i += SORT_T)
        g_rank[base + i] = (unsigned short)(NN - 1 - (unsigned)(keys[i] & 0xFFFu));
}

// ============================================================
// Kernel 3: expert-preferred assignment, latency-optimized.
// 1 block / batch, 256 threads. Register-resident `picked` via
// __syncthreads_count; gmem rank windows with double prefetch;
// smem byte map s_expert; single gather pass at the end.
// ============================================================
#define AT 256
__global__ __launch_bounds__(AT)
void assign_tokens(const float* __restrict__ c, float* __restrict__ out) {
    __shared__ unsigned char s_expert[NN];     // 0xFF = unassigned
    __shared__ int s_warpsum[AT/32];
    __shared__ float s_c[EE];

    const int tid = threadIdx.x;
    const int b = blockIdx.x;
    const int lane = tid & 31, wid = tid >> 5;

    for (int i = tid; i < NN; i += AT) s_expert[i] = 0xFF;
    if (tid < EE) s_c[tid] = c[tid];

    // prefetch expert 63's first window
    unsigned rcur = g_rank[((size_t)(b * EE + 63) << 12) + tid];
    __syncthreads();

    for (int j = EE - 1; j >= 0; --j) {
        // prefetch next expert's first window (hidden under this expert's windows)
        unsigned rnextexp = 0;
        if (j > 0)
            rnextexp = g_rank[((size_t)(b * EE + j - 1) << 12) + tid];

        int kj = (int)floorf(s_c[j] * (float)NN);
        if (kj > NN) kj = NN;
        const size_t rbase = (size_t)(b * EE + j) << 12;

        int picked = 0;
        unsigned r = rcur;
        if (kj > 0) {
            for (int pos = 0; pos < NN && picked < kj; pos += AT) {
                unsigned tok = r;
                bool avail = (s_expert[tok] == 0xFF);
                // prefetch next window
                unsigned rnext = 0;
                if (pos + AT < NN)
                    rnext = g_rank[rbase + pos + AT + tid];

                int total = __syncthreads_count(avail);
                if (picked + total <= kj) {
                    // fast path: accept every available token in this window
                    if (avail) s_expert[tok] = (unsigned char)j;
                    picked += total;
                } else {
                    // cutoff window: need the prefix rank
                    unsigned ball = __ballot_sync(0xFFFFFFFFu, avail);
                    if (lane == 0) s_warpsum[wid] = __popc(ball);
                    __syncthreads();
                    int off = 0;
#pragma unroll
                    for (int w = 0; w < AT/32; w++)
                        if (w < wid) off += s_warpsum[w];
                    int myrank = off + __popc(ball & ((1u << lane) - 1));
                    if (avail && picked + myrank < kj)
                        s_expert[tok] = (unsigned char)j;
                    picked = kj;
                }
                __syncthreads();   // order s_expert writes before next window's reads
                r = rnext;
            }
        }
        rcur = rnextexp;
    }

    // final gather: M + M_probs in one pass (scattered prob loads, MLP ~16)
    for (int n = tid; n < NN; n += AT) {
        unsigned e = s_expert[n];
        if (e == 0xFF) e = 0;
        out[b * NN + n] = (float)e;
        out[TOKENS + b * NN + n] = g_probsT[((size_t)(b * EE + e) << 12) + n];
    }
}

// ============================================================
extern "C" void kernel_launch(void* const* d_in, const int* in_sizes, int n_in,
                              void* d_out, int out_size) {
    const float* x = (const float*)d_in[0];
    const float* W = (const float*)d_in[1];
    const float* c = (const float*)d_in[2];
    float* out = (float*)d_out;

    cudaFuncSetAttribute(router_gemm_mma,
                         cudaFuncAttributeMaxDynamicSharedMemorySize, SMEM_DYN);

    split_w<<<(EE * DD + 255) / 256, 256>>>(W);
    router_gemm_mma<<<TOKENS / TILE_M, 256, SMEM_DYN>>>(x);
    expert_sort<<<BB * EE, SORT_T>>>();
    assign_tokens<<<BB, AT>>>(c, out);
}

// round 8
// speedup vs baseline: 3.3751x; 1.2400x over previous
#include <cuda_runtime.h>
#include <cuda_bf16.h>
#include <cstdint>
#include <math.h>

// ---------------- problem constants ----------------
#define BB 4
#define NN 4096
#define DD 4096
#define EE 64
#define TOKENS (BB*NN)     // 16384

#define KC 64              // K per chunk
#define NCHUNK (DD/KC)     // 64
#define TILE_M 128         // tokens per CTA

// per stage: A planes 3*16KB (128x64 bf16 h/m/l) + B planes 3*8KB (64x64 bf16)
#define A_PLANE 16384
#define B_PLANE 8192
#define B_BASE  (3*A_PLANE)          // 49152
#define STG_BYTES (3*A_PLANE + 3*B_PLANE)   // 73728
#define SMEM_DYN (2*STG_BYTES + 1024)

// ---------------- scratch ----------------
__device__ float          g_probsT[BB*EE*NN];     // [b][e][n]  4MB
__device__ unsigned short g_rank  [BB*EE*NN];     // sorted token ids per (b,e)  2MB
__device__ __nv_bfloat16  g_Wh[EE*DD];
__device__ __nv_bfloat16  g_Wm[EE*DD];
__device__ __nv_bfloat16  g_Wl[EE*DD];

// ---------------- helpers ----------------
__device__ __forceinline__ uint32_t smem_u32(const void* p) {
    uint32_t a;
    asm("{ .reg .u64 t; cvta.to.shared.u64 t, %1; cvt.u32.u64 %0, t; }" : "=r"(a) : "l"(p));
    return a;
}
#define SWZ(off) ((off) ^ (((off) >> 3) & 0x70))

__device__ __forceinline__ void sts64(uint32_t addr, uint32_t a, uint32_t b) {
    asm volatile("st.shared.v2.b32 [%0], {%1,%2};" :: "r"(addr), "r"(a), "r"(b));
}
__device__ __forceinline__ uint32_t pk2(float a, float b) {
    __nv_bfloat162 t = __floats2bfloat162_rn(a, b);   // low = a, high = b
    return *reinterpret_cast<uint32_t*>(&t);
}
__device__ __forceinline__ void ldsm4(uint32_t addr, uint32_t* r) {
    asm volatile("ldmatrix.sync.aligned.m8n8.x4.shared.b16 {%0,%1,%2,%3}, [%4];"
        : "=r"(r[0]), "=r"(r[1]), "=r"(r[2]), "=r"(r[3]) : "r"(addr));
}
__device__ __forceinline__ void mma16816(float* c, const uint32_t* a, const uint32_t* b) {
    asm volatile(
        "mma.sync.aligned.m16n8k16.row.col.f32.bf16.bf16.f32 "
        "{%0,%1,%2,%3},{%4,%5,%6,%7},{%8,%9},{%0,%1,%2,%3};"
        : "+f"(c[0]), "+f"(c[1]), "+f"(c[2]), "+f"(c[3])
        : "r"(a[0]), "r"(a[1]), "r"(a[2]), "r"(a[3]), "r"(b[0]), "r"(b[1]));
}

// ============================================================
// Kernel 0: split W (fp32) into 3 bf16 residual terms.
// ============================================================
__global__ __launch_bounds__(256)
void split_w(const float* __restrict__ W) {
    int i = blockIdx.x * 256 + threadIdx.x;
    if (i >= EE * DD) return;
    float w = W[i];
    __nv_bfloat16 h = __float2bfloat16(w);
    float r = w - __bfloat162float(h);
    __nv_bfloat16 m = __float2bfloat16(r);
    float r2 = r - __bfloat162float(m);
    g_Wh[i] = h;
    g_Wm[i] = m;
    g_Wl[i] = __float2bfloat16(r2);
}

// ============================================================
// Kernel 1: mma.sync bf16x3 router GEMM + fused softmax.
// CTA: 128 tokens x 64 experts, 256 threads (8 warps).
// ============================================================
__global__ __launch_bounds__(256, 1)
void router_gemm_mma(const float* __restrict__ x) {
    extern __shared__ char dsm[];
    const int tid  = threadIdx.x;
    const int wid  = tid >> 5;
    const int lane = tid & 31;
    const int tok0 = blockIdx.x * TILE_M;

    uint32_t sbase = smem_u32(dsm);
    sbase = (sbase + 1023) & ~1023u;

    float acc[8][4];
#pragma unroll
    for (int t = 0; t < 8; t++)
#pragma unroll
        for (int i = 0; i < 4; i++) acc[t][i] = 0.f;

    const int ra    = wid * 16 + (lane & 15);
    const int ahalf = (lane >> 4) * 16;
    const int rb    = (lane & 7) + ((lane >> 4) & 1) * 8;
    const int bhalf = ((lane >> 3) & 1) * 16;

    float4 xa[8];
    uint2 wbh[4], wbm[4], wbl[4];

#pragma unroll
    for (int it = 0; it < 8; ++it) {
        int lin = tid + it * 256, row = lin >> 4, c4 = lin & 15;
        xa[it] = *reinterpret_cast<const float4*>(
            x + (size_t)(tok0 + row) * DD + c4 * 4);
    }
#pragma unroll
    for (int it = 0; it < 4; ++it) {
        int lin = tid + it * 256, row = lin >> 4, cc = lin & 15;
        size_t off = (size_t)row * DD + cc * 4;
        wbh[it] = *reinterpret_cast<const uint2*>(g_Wh + off);
        wbm[it] = *reinterpret_cast<const uint2*>(g_Wm + off);
        wbl[it] = *reinterpret_cast<const uint2*>(g_Wl + off);
    }

#pragma unroll 1
    for (int c = 0; c < NCHUNK; ++c) {
        const uint32_t st = sbase + (c & 1) * STG_BYTES;

#pragma unroll
        for (int it = 0; it < 8; ++it) {
            int lin = tid + it * 256, row = lin >> 4, c4 = lin & 15;
            uint32_t boff = SWZ(row * 128 + c4 * 8);
            float v0 = xa[it].x, v1 = xa[it].y, v2 = xa[it].z, v3 = xa[it].w;
            float h0 = __bfloat162float(__float2bfloat16(v0));
            float h1 = __bfloat162float(__float2bfloat16(v1));
            float h2 = __bfloat162float(__float2bfloat16(v2));
            float h3 = __bfloat162float(__float2bfloat16(v3));
            float r0 = v0 - h0, r1 = v1 - h1, r2 = v2 - h2, r3 = v3 - h3;
            float m0 = __bfloat162float(__float2bfloat16(r0));
            float m1 = __bfloat162float(__float2bfloat16(r1));
            float m2 = __bfloat162float(__float2bfloat16(r2));
            float m3 = __bfloat162float(__float2bfloat16(r3));
            sts64(st +            boff, pk2(h0, h1), pk2(h2, h3));
            sts64(st + A_PLANE  + boff, pk2(m0, m1), pk2(m2, m3));
            sts64(st + 2*A_PLANE+ boff, pk2(r0 - m0, r1 - m1), pk2(r2 - m2, r3 - m3));
        }
#pragma unroll
        for (int it = 0; it < 4; ++it) {
            int lin = tid + it * 256, row = lin >> 4, cc = lin & 15;
            uint32_t boff = SWZ(row * 128 + cc * 8);
            sts64(st + B_BASE            + boff, wbh[it].x, wbh[it].y);
            sts64(st + B_BASE + B_PLANE  + boff, wbm[it].x, wbm[it].y);
            sts64(st + B_BASE + 2*B_PLANE+ boff, wbl[it].x, wbl[it].y);
        }
        __syncthreads();

        if (c + 1 < NCHUNK) {
            const int kc = (c + 1) * KC;
#pragma unroll
            for (int it = 0; it < 8; ++it) {
                int lin = tid + it * 256, row = lin >> 4, c4 = lin & 15;
                xa[it] = *reinterpret_cast<const float4*>(
                    x + (size_t)(tok0 + row) * DD + kc + c4 * 4);
            }
#pragma unroll
            for (int it = 0; it < 4; ++it) {
                int lin = tid + it * 256, row = lin >> 4, cc = lin & 15;
                size_t off = (size_t)row * DD + kc + cc * 4;
                wbh[it] = *reinterpret_cast<const uint2*>(g_Wh + off);
                wbm[it] = *reinterpret_cast<const uint2*>(g_Wm + off);
                wbl[it] = *reinterpret_cast<const uint2*>(g_Wl + off);
            }
        }

#pragma unroll
        for (int k = 0; k < 4; ++k) {
            uint32_t Ah[4], Am[4], Al[4];
            uint32_t aoff = SWZ(ra * 128 + k * 32 + ahalf);
            ldsm4(st +             aoff, Ah);
            ldsm4(st + A_PLANE   + aoff, Am);
            ldsm4(st + 2*A_PLANE + aoff, Al);

            uint32_t Bf[16];
#pragma unroll
            for (int t2 = 0; t2 < 4; ++t2)
                ldsm4(st + B_BASE + SWZ((t2 * 16 + rb) * 128 + k * 32 + bhalf), Bf + 4 * t2);
#pragma unroll
            for (int nt = 0; nt < 8; ++nt) mma16816(acc[nt], Ah, Bf + 2 * nt);
#pragma unroll
            for (int nt = 0; nt < 8; ++nt) mma16816(acc[nt], Am, Bf + 2 * nt);
#pragma unroll
            for (int nt = 0; nt < 8; ++nt) mma16816(acc[nt], Al, Bf + 2 * nt);
#pragma unroll
            for (int t2 = 0; t2 < 4; ++t2)
                ldsm4(st + B_BASE + B_PLANE + SWZ((t2 * 16 + rb) * 128 + k * 32 + bhalf), Bf + 4 * t2);
#pragma unroll
            for (int nt = 0; nt < 8; ++nt) mma16816(acc[nt], Ah, Bf + 2 * nt);
#pragma unroll
            for (int nt = 0; nt < 8; ++nt) mma16816(acc[nt], Am, Bf + 2 * nt);
#pragma unroll
            for (int t2 = 0; t2 < 4; ++t2)
                ldsm4(st + B_BASE + 2*B_PLANE + SWZ((t2 * 16 + rb) * 128 + k * 32 + bhalf), Bf + 4 * t2);
#pragma unroll
            for (int nt = 0; nt < 8; ++nt) mma16816(acc[nt], Ah, Bf + 2 * nt);
        }
    }
    __syncthreads();

    float* ls = reinterpret_cast<float*>(dsm);
    {
        int r0 = wid * 16 + (lane >> 2);
        int cb = 2 * (lane & 3);
#pragma unroll
        for (int nt = 0; nt < 8; ++nt) {
            ls[r0 * 65 + 8 * nt + cb]           = acc[nt][0];
            ls[r0 * 65 + 8 * nt + cb + 1]       = acc[nt][1];
            ls[(r0 + 8) * 65 + 8 * nt + cb]     = acc[nt][2];
            ls[(r0 + 8) * 65 + 8 * nt + cb + 1] = acc[nt][3];
        }
    }
    __syncthreads();

    if (tid < TILE_M) {
        const int t = tid;
        float mx = -INFINITY;
#pragma unroll
        for (int e = 0; e < EE; e++) mx = fmaxf(mx, ls[t * 65 + e]);
        float sum = 0.f;
#pragma unroll
        for (int e = 0; e < EE; e++) {
            float v = expf(ls[t * 65 + e] - mx);
            ls[t * 65 + e] = v;
            sum += v;
        }
        float inv = 1.0f / sum;
        int token = tok0 + t;
        int b = token >> 12, n = token & (NN - 1);
#pragma unroll
        for (int e = 0; e < EE; e++)
            g_probsT[((size_t)(b * EE + e) << 12) + n] = ls[t * 65 + e] * inv;
    }
}

// ============================================================
// Kernel 2: per-(b,e) stable LSD radix sort, descending prob,
// ties -> lower token index (via stability on inverted bits).
// 512 threads; each warp owns a contiguous 256-element segment,
// so global order = (warp, round, lane) = position order.
// ============================================================
#define RS_T 512
// dyn smem: k0 16384 | v0 8192 | k1 16384 | v1 8192 | wh 16384 | aux 32
#define RSM_V0  16384
#define RSM_K1  24576
#define RSM_V1  40960
#define RSM_WH  49152
#define RSM_AUX 65536
#define SMEM_SORT (65536 + 32)

__global__ __launch_bounds__(RS_T)
void expert_sort_radix() {
    extern __shared__ char sm[];
    uint32_t* k0  = reinterpret_cast<uint32_t*>(sm);
    uint16_t* v0  = reinterpret_cast<uint16_t*>(sm + RSM_V0);
    uint32_t* k1  = reinterpret_cast<uint32_t*>(sm + RSM_K1);
    uint16_t* v1  = reinterpret_cast<uint16_t*>(sm + RSM_V1);
    uint32_t* wh  = reinterpret_cast<uint32_t*>(sm + RSM_WH);   // [16][256]
    uint32_t* aux = reinterpret_cast<uint32_t*>(sm + RSM_AUX);  // [8]

    const int tid  = threadIdx.x;
    const int wid  = tid >> 5;
    const int lane = tid & 31;
    const size_t base = (size_t)blockIdx.x << 12;

    for (int i = tid; i < NN; i += RS_T) {
        k0[i] = ~__float_as_uint(g_probsT[base + i]);  // ascending sort of ~bits = descending prob
        v0[i] = (uint16_t)i;
    }
    __syncthreads();

    uint32_t* ks = k0; uint32_t* kd = k1;
    uint16_t* vs = v0; uint16_t* vd = v1;

#pragma unroll 1
    for (int pass = 0; pass < 4; ++pass) {
        const int sh = pass * 8;

        for (int i = tid; i < 16 * 256; i += RS_T) wh[i] = 0;
        __syncthreads();

        // ---- count (per-warp histograms over this warp's 256-el segment) ----
#pragma unroll
        for (int r = 0; r < 8; ++r) {
            uint32_t d = (ks[wid * 256 + r * 32 + lane] >> sh) & 255u;
            atomicAdd(&wh[wid * 256 + d], 1u);
        }
        __syncthreads();

        // ---- scan: digit totals -> exclusive bin starts -> per-warp starts ----
        uint32_t t = 0, s = 0;
        if (tid < 256) {
#pragma unroll
            for (int w = 0; w < 16; ++w) t += wh[w * 256 + tid];
            s = t;
#pragma unroll
            for (int o = 1; o < 32; o <<= 1) {
                uint32_t n = __shfl_up_sync(0xFFFFFFFFu, s, o);
                if (lane >= o) s += n;
            }
            if (lane == 31) aux[wid] = s;
        }
        __syncthreads();
        if (tid == 0) {
            uint32_t run = 0;
#pragma unroll
            for (int i = 0; i < 8; ++i) { uint32_t c2 = aux[i]; aux[i] = run; run += c2; }
        }
        __syncthreads();
        if (tid < 256) {
            uint32_t run = s - t + aux[wid];   // exclusive global start for digit `tid`
#pragma unroll
            for (int w = 0; w < 16; ++w) {
                uint32_t c2 = wh[w * 256 + tid];
                wh[w * 256 + tid] = run;
                run += c2;
            }
        }
        __syncthreads();

        // ---- stable scatter: rounds in segment order; warp-private counters ----
#pragma unroll
        for (int r = 0; r < 8; ++r) {
            int idx = wid * 256 + r * 32 + lane;
            uint32_t key = ks[idx];
            uint32_t val = vs[idx];
            uint32_t d = (key >> sh) & 255u;
            uint32_t mask = __match_any_sync(0xFFFFFFFFu, d);
            int leader = __ffs(mask) - 1;
            uint32_t bse = 0;
            if (lane == leader) bse = wh[wid * 256 + d];
            bse = __shfl_sync(0xFFFFFFFFu, bse, leader);
            uint32_t rank = bse + __popc(mask & ((1u << lane) - 1));
            if (lane == leader) wh[wid * 256 + d] = bse + __popc(mask);
            kd[rank] = key;
            vd[rank] = (uint16_t)val;
            __syncwarp();
        }
        __syncthreads();

        uint32_t* tk = ks; ks = kd; kd = tk;
        uint16_t* tv = vs; vs = vd; vd = tv;
    }

    for (int i = tid; i < NN; i += RS_T)
        g_rank[base + i] = vs[i];
}

// ============================================================
// Kernel 3: expert-preferred assignment. 1 block/batch, 512 thr,
// 512-token windows, 2-expert-deep rank prefetch, smem byte map,
// single gather pass.
// ============================================================
#define AT 512
__global__ __launch_bounds__(AT)
void assign_tokens(const float* __restrict__ c, float* __restrict__ out) {
    __shared__ unsigned char s_expert[NN];     // 0xFF = unassigned
    __shared__ int s_warpsum[AT/32];
    __shared__ float s_c[EE];

    const int tid = threadIdx.x;
    const int b = blockIdx.x;
    const int lane = tid & 31, wid = tid >> 5;

    for (int i = tid; i < NN; i += AT) s_expert[i] = 0xFF;
    if (tid < EE) s_c[tid] = c[tid];

    // 2-deep prefetch of expert window-0 ranks
    unsigned rcur = g_rank[((size_t)(b * EE + 63) << 12) + tid];
    unsigned rnx  = g_rank[((size_t)(b * EE + 62) << 12) + tid];
    __syncthreads();

    for (int j = EE - 1; j >= 0; --j) {
        unsigned rfut = 0;
        if (j >= 2)
            rfut = g_rank[((size_t)(b * EE + j - 2) << 12) + tid];

        int kj = (int)floorf(s_c[j] * (float)NN);
        if (kj > NN) kj = NN;
        const size_t rbase = (size_t)(b * EE + j) << 12;

        if (kj > 0) {
            int picked = 0;
            unsigned r = rcur;
            for (int pos = 0; pos < NN && picked < kj; pos += AT) {
                unsigned tok = r;
                bool avail = (s_expert[tok] == 0xFF);
                unsigned rnext = 0;
                if (pos + AT < NN)
                    rnext = g_rank[rbase + pos + AT + tid];

                int total = __syncthreads_count(avail);
                if (picked + total <= kj) {
                    if (avail) s_expert[tok] = (unsigned char)j;
                    picked += total;
                } else {
                    unsigned ball = __ballot_sync(0xFFFFFFFFu, avail);
                    if (lane == 0) s_warpsum[wid] = __popc(ball);
                    __syncthreads();
                    int off = 0;
#pragma unroll
                    for (int w = 0; w < AT/32; w++)
                        if (w < wid) off += s_warpsum[w];
                    int myrank = off + __popc(ball & ((1u << lane) - 1));
                    if (avail && picked + myrank < kj)
                        s_expert[tok] = (unsigned char)j;
                    picked = kj;
                }
                __syncthreads();
                r = rnext;
            }
        }
        rcur = rnx;
        rnx = rfut;
    }

    for (int n = tid; n < NN; n += AT) {
        unsigned e = s_expert[n];
        if (e == 0xFF) e = 0;
        out[b * NN + n] = (float)e;
        out[TOKENS + b * NN + n] = g_probsT[((size_t)(b * EE + e) << 12) + n];
    }
}

// ============================================================
extern "C" void kernel_launch(void* const* d_in, const int* in_sizes, int n_in,
                              void* d_out, int out_size) {
    const float* x = (const float*)d_in[0];
    const float* W = (const float*)d_in[1];
    const float* c = (const float*)d_in[2];
    float* out = (float*)d_out;

    cudaFuncSetAttribute(router_gemm_mma,
                         cudaFuncAttributeMaxDynamicSharedMemorySize, SMEM_DYN);
    cudaFuncSetAttribute(expert_sort_radix,
                         cudaFuncAttributeMaxDynamicSharedMemorySize, SMEM_SORT);

    split_w<<<(EE * DD + 255) / 256, 256>>>(W);
    router_gemm_mma<<<TOKENS / TILE_M, 256, SMEM_DYN>>>(x);
    expert_sort_radix<<<BB * EE, RS_T, SMEM_SORT>>>();
    assign_tokens<<<BB, AT>>>(c, out);
}

// round 10
// speedup vs baseline: 3.3989x; 1.0070x over previous
#include <cuda_runtime.h>
#include <cuda_bf16.h>
#include <cstdint>
#include <math.h>

// ---------------- problem constants ----------------
#define BB 4
#define NN 4096
#define DD 4096
#define EE 64
#define TOKENS (BB*NN)     // 16384

#define KC 64              // K per chunk
#define NCHUNK (DD/KC)     // 64
#define TILE_M 128         // tokens per CTA

// per stage: A planes 3*16KB (128x64 bf16 h/m/l) + B planes 3*8KB (64x64 bf16)
#define A_PLANE 16384
#define B_PLANE 8192
#define B_BASE  (3*A_PLANE)          // 49152
#define STG_BYTES (3*A_PLANE + 3*B_PLANE)   // 73728
#define SMEM_DYN (2*STG_BYTES + 1024)

// ---------------- scratch ----------------
__device__ float          g_probsT[BB*EE*NN];     // [b][e][n]  4MB
__device__ unsigned short g_rank  [BB*EE*NN];     // sorted token ids per (b,e)  2MB
__device__ __nv_bfloat16  g_Wh[EE*DD];
__device__ __nv_bfloat16  g_Wm[EE*DD];
__device__ __nv_bfloat16  g_Wl[EE*DD];

// ---------------- helpers ----------------
__device__ __forceinline__ uint32_t smem_u32(const void* p) {
    uint32_t a;
    asm("{ .reg .u64 t; cvta.to.shared.u64 t, %1; cvt.u32.u64 %0, t; }" : "=r"(a) : "l"(p));
    return a;
}
#define SWZ(off) ((off) ^ (((off) >> 3) & 0x70))

__device__ __forceinline__ void sts64(uint32_t addr, uint32_t a, uint32_t b) {
    asm volatile("st.shared.v2.b32 [%0], {%1,%2};" :: "r"(addr), "r"(a), "r"(b));
}
__device__ __forceinline__ uint32_t pk2(float a, float b) {
    __nv_bfloat162 t = __floats2bfloat162_rn(a, b);   // low = a, high = b
    return *reinterpret_cast<uint32_t*>(&t);
}
__device__ __forceinline__ void ldsm4(uint32_t addr, uint32_t* r) {
    asm volatile("ldmatrix.sync.aligned.m8n8.x4.shared.b16 {%0,%1,%2,%3}, [%4];"
        : "=r"(r[0]), "=r"(r[1]), "=r"(r[2]), "=r"(r[3]) : "r"(addr));
}
__device__ __forceinline__ void mma16816(float* c, const uint32_t* a, const uint32_t* b) {
    asm volatile(
        "mma.sync.aligned.m16n8k16.row.col.f32.bf16.bf16.f32 "
        "{%0,%1,%2,%3},{%4,%5,%6,%7},{%8,%9},{%0,%1,%2,%3};"
        : "+f"(c[0]), "+f"(c[1]), "+f"(c[2]), "+f"(c[3])
        : "r"(a[0]), "r"(a[1]), "r"(a[2]), "r"(a[3]), "r"(b[0]), "r"(b[1]));
}
__device__ __forceinline__ void cp_async16(uint32_t sdst, const void* gsrc) {
    asm volatile("cp.async.cg.shared.global [%0], [%1], 16;" :: "r"(sdst), "l"(gsrc));
}
#define CP_COMMIT() asm volatile("cp.async.commit_group;" ::: "memory")
#define CP_WAIT1()  asm volatile("cp.async.wait_group 1;" ::: "memory")
#define CP_WAIT0()  asm volatile("cp.async.wait_group 0;" ::: "memory")

// ============================================================
// Kernel 0: split W (fp32) into 3 bf16 residual terms.
// ============================================================
__global__ __launch_bounds__(256)
void split_w(const float* __restrict__ W) {
    int i = blockIdx.x * 256 + threadIdx.x;
    if (i >= EE * DD) return;
    float w = W[i];
    __nv_bfloat16 h = __float2bfloat16(w);
    float r = w - __bfloat162float(h);
    __nv_bfloat16 m = __float2bfloat16(r);
    float r2 = r - __bfloat162float(m);
    g_Wh[i] = h;
    g_Wm[i] = m;
    g_Wl[i] = __float2bfloat16(r2);
}

// ============================================================
// Kernel 1: mma.sync bf16x3 router GEMM + fused softmax.
// CTA: 128 tokens x 64 experts, 256 threads (8 warps).
// ============================================================
__global__ __launch_bounds__(256, 1)
void router_gemm_mma(const float* __restrict__ x) {
    extern __shared__ char dsm[];
    const int tid  = threadIdx.x;
    const int wid  = tid >> 5;
    const int lane = tid & 31;
    const int tok0 = blockIdx.x * TILE_M;

    uint32_t sbase = smem_u32(dsm);
    sbase = (sbase + 1023) & ~1023u;

    float acc[8][4];
#pragma unroll
    for (int t = 0; t < 8; t++)
#pragma unroll
        for (int i = 0; i < 4; i++) acc[t][i] = 0.f;

    const int ra    = wid * 16 + (lane & 15);
    const int ahalf = (lane >> 4) * 16;
    const int rb    = (lane & 7) + ((lane >> 4) & 1) * 8;
    const int bhalf = ((lane >> 3) & 1) * 16;

    float4 xa[8];
    uint2 wbh[4], wbm[4], wbl[4];

#pragma unroll
    for (int it = 0; it < 8; ++it) {
        int lin = tid + it * 256, row = lin >> 4, c4 = lin & 15;
        xa[it] = *reinterpret_cast<const float4*>(
            x + (size_t)(tok0 + row) * DD + c4 * 4);
    }
#pragma unroll
    for (int it = 0; it < 4; ++it) {
        int lin = tid + it * 256, row = lin >> 4, cc = lin & 15;
        size_t off = (size_t)row * DD + cc * 4;
        wbh[it] = *reinterpret_cast<const uint2*>(g_Wh + off);
        wbm[it] = *reinterpret_cast<const uint2*>(g_Wm + off);
        wbl[it] = *reinterpret_cast<const uint2*>(g_Wl + off);
    }

#pragma unroll 1
    for (int c = 0; c < NCHUNK; ++c) {
        const uint32_t st = sbase + (c & 1) * STG_BYTES;

#pragma unroll
        for (int it = 0; it < 8; ++it) {
            int lin = tid + it * 256, row = lin >> 4, c4 = lin & 15;
            uint32_t boff = SWZ(row * 128 + c4 * 8);
            float v0 = xa[it].x, v1 = xa[it].y, v2 = xa[it].z, v3 = xa[it].w;
            float h0 = __bfloat162float(__float2bfloat16(v0));
            float h1 = __bfloat162float(__float2bfloat16(v1));
            float h2 = __bfloat162float(__float2bfloat16(v2));
            float h3 = __bfloat162float(__float2bfloat16(v3));
            float r0 = v0 - h0, r1 = v1 - h1, r2 = v2 - h2, r3 = v3 - h3;
            float m0 = __bfloat162float(__float2bfloat16(r0));
            float m1 = __bfloat162float(__float2bfloat16(r1));
            float m2 = __bfloat162float(__float2bfloat16(r2));
            float m3 = __bfloat162float(__float2bfloat16(r3));
            sts64(st +            boff, pk2(h0, h1), pk2(h2, h3));
            sts64(st + A_PLANE  + boff, pk2(m0, m1), pk2(m2, m3));
            sts64(st + 2*A_PLANE+ boff, pk2(r0 - m0, r1 - m1), pk2(r2 - m2, r3 - m3));
        }
#pragma unroll
        for (int it = 0; it < 4; ++it) {
            int lin = tid + it * 256, row = lin >> 4, cc = lin & 15;
            uint32_t boff = SWZ(row * 128 + cc * 8);
            sts64(st + B_BASE            + boff, wbh[it].x, wbh[it].y);
            sts64(st + B_BASE + B_PLANE  + boff, wbm[it].x, wbm[it].y);
            sts64(st + B_BASE + 2*B_PLANE+ boff, wbl[it].x, wbl[it].y);
        }
        __syncthreads();

        if (c + 1 < NCHUNK) {
            const int kc = (c + 1) * KC;
#pragma unroll
            for (int it = 0; it < 8; ++it) {
                int lin = tid + it * 256, row = lin >> 4, c4 = lin & 15;
                xa[it] = *reinterpret_cast<const float4*>(
                    x + (size_t)(tok0 + row) * DD + kc + c4 * 4);
            }
#pragma unroll
            for (int it = 0; it < 4; ++it) {
                int lin = tid + it * 256, row = lin >> 4, cc = lin & 15;
                size_t off = (size_t)row * DD + kc + cc * 4;
                wbh[it] = *reinterpret_cast<const uint2*>(g_Wh + off);
                wbm[it] = *reinterpret_cast<const uint2*>(g_Wm + off);
                wbl[it] = *reinterpret_cast<const uint2*>(g_Wl + off);
            }
        }

#pragma unroll
        for (int k = 0; k < 4; ++k) {
            uint32_t Ah[4], Am[4], Al[4];
            uint32_t aoff = SWZ(ra * 128 + k * 32 + ahalf);
            ldsm4(st +             aoff, Ah);
            ldsm4(st + A_PLANE   + aoff, Am);
            ldsm4(st + 2*A_PLANE + aoff, Al);

            uint32_t Bf[16];
#pragma unroll
            for (int t2 = 0; t2 < 4; ++t2)
                ldsm4(st + B_BASE + SWZ((t2 * 16 + rb) * 128 + k * 32 + bhalf), Bf + 4 * t2);
#pragma unroll
            for (int nt = 0; nt < 8; ++nt) mma16816(acc[nt], Ah, Bf + 2 * nt);
#pragma unroll
            for (int nt = 0; nt < 8; ++nt) mma16816(acc[nt], Am, Bf + 2 * nt);
#pragma unroll
            for (int nt = 0; nt < 8; ++nt) mma16816(acc[nt], Al, Bf + 2 * nt);
#pragma unroll
            for (int t2 = 0; t2 < 4; ++t2)
                ldsm4(st + B_BASE + B_PLANE + SWZ((t2 * 16 + rb) * 128 + k * 32 + bhalf), Bf + 4 * t2);
#pragma unroll
            for (int nt = 0; nt < 8; ++nt) mma16816(acc[nt], Ah, Bf + 2 * nt);
#pragma unroll
            for (int nt = 0; nt < 8; ++nt) mma16816(acc[nt], Am, Bf + 2 * nt);
#pragma unroll
            for (int t2 = 0; t2 < 4; ++t2)
                ldsm4(st + B_BASE + 2*B_PLANE + SWZ((t2 * 16 + rb) * 128 + k * 32 + bhalf), Bf + 4 * t2);
#pragma unroll
            for (int nt = 0; nt < 8; ++nt) mma16816(acc[nt], Ah, Bf + 2 * nt);
        }
    }
    __syncthreads();

    float* ls = reinterpret_cast<float*>(dsm);
    {
        int r0 = wid * 16 + (lane >> 2);
        int cb = 2 * (lane & 3);
#pragma unroll
        for (int nt = 0; nt < 8; ++nt) {
            ls[r0 * 65 + 8 * nt + cb]           = acc[nt][0];
            ls[r0 * 65 + 8 * nt + cb + 1]       = acc[nt][1];
            ls[(r0 + 8) * 65 + 8 * nt + cb]     = acc[nt][2];
            ls[(r0 + 8) * 65 + 8 * nt + cb + 1] = acc[nt][3];
        }
    }
    __syncthreads();

    if (tid < TILE_M) {
        const int t = tid;
        float mx = -INFINITY;
#pragma unroll
        for (int e = 0; e < EE; e++) mx = fmaxf(mx, ls[t * 65 + e]);
        float sum = 0.f;
#pragma unroll
        for (int e = 0; e < EE; e++) {
            float v = expf(ls[t * 65 + e] - mx);
            ls[t * 65 + e] = v;
            sum += v;
        }
        float inv = 1.0f / sum;
        int token = tok0 + t;
        int b = token >> 12, n = token & (NN - 1);
#pragma unroll
        for (int e = 0; e < EE; e++)
            g_probsT[((size_t)(b * EE + e) << 12) + n] = ls[t * 65 + e] * inv;
    }
}

// ============================================================
// Kernel 2: per-(b,e) stable LSD radix sort, descending prob,
// ties -> lower token index (via stability on inverted bits).
// ============================================================
#define RS_T 512
#define RSM_V0  16384
#define RSM_K1  24576
#define RSM_V1  40960
#define RSM_WH  49152
#define RSM_AUX 65536
#define SMEM_SORT (65536 + 32)

__global__ __launch_bounds__(RS_T)
void expert_sort_radix() {
    extern __shared__ char sm[];
    uint32_t* k0  = reinterpret_cast<uint32_t*>(sm);
    uint16_t* v0  = reinterpret_cast<uint16_t*>(sm + RSM_V0);
    uint32_t* k1  = reinterpret_cast<uint32_t*>(sm + RSM_K1);
    uint16_t* v1  = reinterpret_cast<uint16_t*>(sm + RSM_V1);
    uint32_t* wh  = reinterpret_cast<uint32_t*>(sm + RSM_WH);   // [16][256]
    uint32_t* aux = reinterpret_cast<uint32_t*>(sm + RSM_AUX);  // [8]

    const int tid  = threadIdx.x;
    const int wid  = tid >> 5;
    const int lane = tid & 31;
    const size_t base = (size_t)blockIdx.x << 12;

    for (int i = tid; i < NN; i += RS_T) {
        k0[i] = ~__float_as_uint(g_probsT[base + i]);
        v0[i] = (uint16_t)i;
    }
    __syncthreads();

    uint32_t* ks = k0; uint32_t* kd = k1;
    uint16_t* vs = v0; uint16_t* vd = v1;

#pragma unroll 1
    for (int pass = 0; pass < 4; ++pass) {
        const int sh = pass * 8;

        for (int i = tid; i < 16 * 256; i += RS_T) wh[i] = 0;
        __syncthreads();

#pragma unroll
        for (int r = 0; r < 8; ++r) {
            uint32_t d = (ks[wid * 256 + r * 32 + lane] >> sh) & 255u;
            atomicAdd(&wh[wid * 256 + d], 1u);
        }
        __syncthreads();

        uint32_t t = 0, s = 0;
        if (tid < 256) {
#pragma unroll
            for (int w = 0; w < 16; ++w) t += wh[w * 256 + tid];
            s = t;
#pragma unroll
            for (int o = 1; o < 32; o <<= 1) {
                uint32_t n = __shfl_up_sync(0xFFFFFFFFu, s, o);
                if (lane >= o) s += n;
            }
            if (lane == 31) aux[wid] = s;
        }
        __syncthreads();
        if (tid == 0) {
            uint32_t run = 0;
#pragma unroll
            for (int i = 0; i < 8; ++i) { uint32_t c2 = aux[i]; aux[i] = run; run += c2; }
        }
        __syncthreads();
        if (tid < 256) {
            uint32_t run = s - t + aux[wid];
#pragma unroll
            for (int w = 0; w < 16; ++w) {
                uint32_t c2 = wh[w * 256 + tid];
                wh[w * 256 + tid] = run;
                run += c2;
            }
        }
        __syncthreads();

#pragma unroll
        for (int r = 0; r < 8; ++r) {
            int idx = wid * 256 + r * 32 + lane;
            uint32_t key = ks[idx];
            uint32_t val = vs[idx];
            uint32_t d = (key >> sh) & 255u;
            uint32_t mask = __match_any_sync(0xFFFFFFFFu, d);
            int leader = __ffs(mask) - 1;
            uint32_t bse = 0;
            if (lane == leader) bse = wh[wid * 256 + d];
            bse = __shfl_sync(0xFFFFFFFFu, bse, leader);
            uint32_t rank = bse + __popc(mask & ((1u << lane) - 1));
            if (lane == leader) wh[wid * 256 + d] = bse + __popc(mask);
            kd[rank] = key;
            vd[rank] = (uint16_t)val;
            __syncwarp();
        }
        __syncthreads();

        uint32_t* tk = ks; ks = kd; kd = tk;
        uint16_t* tv = vs; vs = vd; vd = tv;
    }

    for (int i = tid; i < NN; i += RS_T)
        g_rank[base + i] = vs[i];
}

// ============================================================
// Kernel 3: expert-preferred assignment. 1 block/batch, 512 thr.
// Full rank rows double-buffered into smem via cp.async so the
// serial window chain is barrier+LDS only. Single gather pass.
// ============================================================
#define AT 512
__global__ __launch_bounds__(AT)
void assign_tokens(const float* __restrict__ c, float* __restrict__ out) {
    __shared__ unsigned char s_expert[NN];                     // 4KB, 0xFF = unassigned
    __shared__ __align__(16) unsigned short s_rank[2][NN];     // 16KB double buffer
    __shared__ int s_warpsum[AT/32];
    __shared__ float s_c[EE];

    const int tid = threadIdx.x;
    const int b = blockIdx.x;
    const int lane = tid & 31, wid = tid >> 5;

    for (int i = tid; i < NN; i += AT) s_expert[i] = 0xFF;
    if (tid < EE) s_c[tid] = c[tid];

    // stage rows 63 (buf0) and 62 (buf1); 8KB = 512 x 16B each
    {
        uint32_t d0 = smem_u32(&s_rank[0][0]) + tid * 16;
        cp_async16(d0, g_rank + ((size_t)(b * EE + 63) << 12) + tid * 8);
        CP_COMMIT();
        uint32_t d1 = smem_u32(&s_rank[1][0]) + tid * 16;
        cp_async16(d1, g_rank + ((size_t)(b * EE + 62) << 12) + tid * 8);
        CP_COMMIT();
    }

    for (int j = EE - 1; j >= 0; --j) {
        const int p = (EE - 1 - j) & 1;

        // row j must be resident: most recent pending group is g(j-1) for j>=1
        if (j >= 1) CP_WAIT1(); else CP_WAIT0();
        __syncthreads();

        int kj = (int)floorf(s_c[j] * (float)NN);
        if (kj > NN) kj = NN;

        if (kj > 0) {
            int picked = 0;
            for (int pos = 0; pos < NN && picked < kj; pos += AT) {
                unsigned tok = s_rank[p][pos + tid];
                bool avail = (s_expert[tok] == 0xFF);

                int total = __syncthreads_count(avail);
                if (picked + total <= kj) {
                    if (avail) s_expert[tok] = (unsigned char)j;
                    picked += total;
                } else {
                    unsigned ball = __ballot_sync(0xFFFFFFFFu, avail);
                    if (lane == 0) s_warpsum[wid] = __popc(ball);
                    __syncthreads();
                    int off = 0;
#pragma unroll
                    for (int w = 0; w < AT/32; w++)
                        if (w < wid) off += s_warpsum[w];
                    int myrank = off + __popc(ball & ((1u << lane) - 1));
                    if (avail && picked + myrank < kj)
                        s_expert[tok] = (unsigned char)j;
                    picked = kj;
                }
                __syncthreads();   // order s_expert writes before next window reads
            }
        }

        // buffer p is now free; stage row j-2 into it (hidden under expert j-1)
        if (j >= 2) {
            __syncthreads();       // all reads of buf p done before overwrite
            uint32_t d = smem_u32(&s_rank[p][0]) + tid * 16;
            cp_async16(d, g_rank + ((size_t)(b * EE + j - 2) << 12) + tid * 8);
            CP_COMMIT();
        }
    }

    // final gather: M + M_probs (scattered prob loads, high MLP)
    for (int n = tid; n < NN; n += AT) {
        unsigned e = s_expert[n];
        if (e == 0xFF) e = 0;
        out[b * NN + n] = (float)e;
        out[TOKENS + b * NN + n] = g_probsT[((size_t)(b * EE + e) << 12) + n];
    }
}

// ============================================================
extern "C" void kernel_launch(void* const* d_in, const int* in_sizes, int n_in,
                              void* d_out, int out_size) {
    const float* x = (const float*)d_in[0];
    const float* W = (const float*)d_in[1];
    const float* c = (const float*)d_in[2];
    float* out = (float*)d_out;

    cudaFuncSetAttribute(router_gemm_mma,
                         cudaFuncAttributeMaxDynamicSharedMemorySize, SMEM_DYN);
    cudaFuncSetAttribute(expert_sort_radix,
                         cudaFuncAttributeMaxDynamicSharedMemorySize, SMEM_SORT);

    split_w<<<(EE * DD + 255) / 256, 256>>>(W);
    router_gemm_mma<<<TOKENS / TILE_M, 256, SMEM_DYN>>>(x);
    expert_sort_radix<<<BB * EE, RS_T, SMEM_SORT>>>();
    assign_tokens<<<BB, AT>>>(c, out);
}